// round 14
// baseline (speedup 1.0000x reference)
#include <cuda_runtime.h>
#include <cuda_bf16.h>
#include <cstdint>

#define NB 4
typedef unsigned long long ull;
typedef unsigned int u32;

// ---------------- scratch ----------------
__device__ float g_om[NB * 27 * 64 * 64];
__device__ float g_y[NB * 128 * 64 * 64];
__device__ float g_up[NB * 128 * 128 * 128];
__device__ float g_woffT[2304 * 32];
__device__ __nv_bfloat16 g_wAH[72 * 4096];     // mdcn A frags hi  [chunk][ks][mt][lane][w][e]
__device__ __nv_bfloat16 g_wAL[72 * 4096];
__device__ __nv_bfloat16 g_wuH[4 * 16 * 4096]; // deconv A frags hi [p][chunk][ks][mt][lane][w][e]
__device__ __nv_bfloat16 g_wuL[4 * 16 * 4096];
__device__ float g_bn1s[128], g_bn1t[128];
__device__ float g_bn2s[128], g_bn2t[128];

// ---------------- helpers ----------------
__device__ __forceinline__ ull dup2(float v) {
    ull r; asm("mov.b64 %0, {%1,%1};" : "=l"(r) : "f"(v)); return r;
}
__device__ __forceinline__ void fma2(ull& d, ull a, ull b) {
    asm("fma.rn.f32x2 %0, %1, %2, %0;" : "+l"(d) : "l"(a), "l"(b));
}
__device__ __forceinline__ float2 unpk(ull v) {
    float2 r; asm("mov.b64 {%0, %1}, %2;" : "=f"(r.x), "=f"(r.y) : "l"(v)); return r;
}
__device__ __forceinline__ void cp16(void* s, const void* g) {
    unsigned sa = (unsigned)__cvta_generic_to_shared(s);
    asm volatile("cp.async.ca.shared.global [%0], [%1], 16;" :: "r"(sa), "l"(g));
}
__device__ __forceinline__ void cp_commit() { asm volatile("cp.async.commit_group;"); }
__device__ __forceinline__ void cp_wait0()  { asm volatile("cp.async.wait_group 0;" ::: "memory"); }

__device__ __forceinline__ u32 smem_u32(const void* p) {
    u32 a; asm("{ .reg .u64 t; cvta.to.shared.u64 t, %1; cvt.u32.u64 %0, t; }" : "=r"(a) : "l"(p));
    return a;
}
__device__ __forceinline__ void ldsm4t(u32* r, u32 addr) {
    asm volatile("ldmatrix.sync.aligned.m8n8.x4.trans.shared.b16 {%0,%1,%2,%3}, [%4];"
                 : "=r"(r[0]), "=r"(r[1]), "=r"(r[2]), "=r"(r[3]) : "r"(addr));
}
__device__ __forceinline__ void mma16816(float* c, const u32* a, u32 b0, u32 b1) {
    asm volatile(
        "mma.sync.aligned.m16n8k16.row.col.f32.bf16.bf16.f32 "
        "{%0,%1,%2,%3}, {%4,%5,%6,%7}, {%8,%9}, {%0,%1,%2,%3};"
        : "+f"(c[0]), "+f"(c[1]), "+f"(c[2]), "+f"(c[3])
        : "r"(a[0]), "r"(a[1]), "r"(a[2]), "r"(a[3]), "r"(b0), "r"(b1));
}

// B tile: [k32][n64], row = 64 bf16 = 128B + 16B pad = 144B pitch
#define PK 144

// ---------------- kernel 0: weights in MMA-fragment order + hi/lo split ----------------
__global__ void __launch_bounds__(256) prep_weights(const float* __restrict__ w_off,
                                                    const float* __restrict__ w_dcn,
                                                    const float* __restrict__ w_up) {
    int idx = blockIdx.x * 256 + threadIdx.x;
    const int NW1 = 72 * 4096;
    const int NW2 = 4 * 16 * 4096;
    if (idx < NW1) {
        int e = idx & 1, w = (idx >> 1) & 3, lane = (idx >> 3) & 31;
        int mt = (idx >> 8) & 7, ks = (idx >> 11) & 1, chunk = idx >> 12;
        int oc = mt * 16 + (w & 1) * 8 + (lane >> 2);
        int k  = chunk * 32 + ks * 16 + (w >> 1) * 8 + (lane & 3) * 2 + e;
        float v = w_dcn[oc * 2304 + k];
        __nv_bfloat16 hi = __float2bfloat16(v);
        __nv_bfloat16 lo = __float2bfloat16(v - __bfloat162float(hi));
        g_wAH[idx] = hi;
        g_wAL[idx] = lo;
        return;
    }
    int i2 = idx - NW1;
    if (i2 < NW2) {
        int e = i2 & 1, w = (i2 >> 1) & 3, lane = (i2 >> 3) & 31;
        int mt = (i2 >> 8) & 7, ks = (i2 >> 11) & 1, chunk = (i2 >> 12) & 15;
        int p = i2 >> 16;
        int oc = mt * 16 + (w & 1) * 8 + (lane >> 2);
        int k  = chunk * 32 + ks * 16 + (w >> 1) * 8 + (lane & 3) * 2 + e;
        int c = k >> 2, tap = k & 3;
        int ty = tap >> 1, tx = tap & 1;
        int pY = p >> 1, pX = p & 1;
        int ky = (pY ^ 1) + 2 * ty;
        int kx = (pX ^ 1) + 2 * tx;
        float v = w_up[((c * 128 + oc) * 4 + ky) * 4 + kx];
        __nv_bfloat16 hi = __float2bfloat16(v);
        __nv_bfloat16 lo = __float2bfloat16(v - __bfloat162float(hi));
        g_wuH[i2] = hi;
        g_wuL[i2] = lo;
        return;
    }
    int i3 = i2 - NW2;
    if (i3 < 2304 * 32) {
        int ck = i3 >> 5, oc = i3 & 31;
        g_woffT[i3] = (oc < 27) ? w_off[oc * 2304 + ck] : 0.f;
    }
}

// ---------------- dummy (ncu capture = idx 3) ----------------
__global__ void dummy_kernel() {}

// ---------------- kernel 1: 3x3 offset conv (SIMT fma2, unchanged) ------------
__global__ void __launch_bounds__(256, 2) conv_off_kernel(const float* __restrict__ x,
                                                          const float* __restrict__ b_off) {
    __shared__ float As[2][36][32];
    __shared__ float Bs[2][36][64];
    int b = blockIdx.x >> 6;
    int h = blockIdx.x & 63;
    int t = threadIdx.x;
    int ocp = t >> 4;
    int pb = (t & 15) << 2;
    const float* xb = x + b * 256 * 4096;
    ull acc[4];
#pragma unroll
    for (int j = 0; j < 4; j++) acc[j] = 0ull;
    float xv[9];

#define COFF_LOADB(c0)                                                          \
    {                                                                           \
        _Pragma("unroll")                                                       \
        for (int i = 0; i < 9; i++) {                                           \
            int e = t + (i << 8);                                               \
            int kc = e >> 6, wx = e & 63;                                       \
            int ci = kc / 9, kk = kc - ci * 9;                                  \
            int ky = kk / 3, kx = kk - ky * 3;                                  \
            int yy = h + ky - 1, xx = wx + kx - 1;                              \
            float v = 0.f;                                                      \
            if ((unsigned)yy < 64u && (unsigned)xx < 64u)                       \
                v = xb[((c0) + ci) * 4096 + yy * 64 + xx];                      \
            xv[i] = v;                                                          \
        }                                                                       \
    }
#define COFF_STOREB(dst)                                                        \
    {                                                                           \
        _Pragma("unroll")                                                       \
        for (int i = 0; i < 9; i++) {                                           \
            int e = t + (i << 8);                                               \
            int kc = e >> 6, wx = e & 63;                                       \
            Bs[dst][kc][wx] = xv[i];                                            \
        }                                                                       \
    }
#define COFF_LOADA(c0, dst)                                                     \
    {                                                                           \
        const float4* wsrc = (const float4*)(g_woffT + (c0) * 9 * 32);          \
        _Pragma("unroll")                                                       \
        for (int i = 0; i < 2; i++) {                                           \
            int e = t + (i << 8);                                               \
            if (e < 288) cp16(&((float4*)As[dst])[e], wsrc + e);                \
        }                                                                       \
        cp_commit();                                                            \
    }
#define COFF_COMPUTE(cc)                                                        \
    {                                                                           \
        _Pragma("unroll")                                                       \
        for (int kc = 0; kc < 36; kc++) {                                       \
            ull Au = *(const ull*)&As[cc][kc][ocp * 2];                         \
            float4 bv = *(const float4*)&Bs[cc][kc][pb];                        \
            fma2(acc[0], Au, dup2(bv.x));                                       \
            fma2(acc[1], Au, dup2(bv.y));                                       \
            fma2(acc[2], Au, dup2(bv.z));                                       \
            fma2(acc[3], Au, dup2(bv.w));                                       \
        }                                                                       \
    }

    int cur = 0;
    COFF_LOADA(0, 0)
    COFF_LOADB(0)
    COFF_STOREB(0)
    cp_wait0();
    __syncthreads();
    for (int c0 = 4; c0 < 256; c0 += 4) {
        int nxt = cur ^ 1;
        COFF_LOADA(c0, nxt)
        COFF_LOADB(c0)
        COFF_COMPUTE(cur)
        COFF_STOREB(nxt)
        cp_wait0();
        __syncthreads();
        cur = nxt;
    }
    COFF_COMPUTE(cur)

    int oc = 2 * ocp;
    if (oc < 27) {
        float2 p0 = unpk(acc[0]), p1 = unpk(acc[1]), p2 = unpk(acc[2]), p3 = unpk(acc[3]);
        float bo = b_off[oc];
        float4 lo = make_float4(p0.x + bo, p1.x + bo, p2.x + bo, p3.x + bo);
        *(float4*)&g_om[((b * 27 + oc) * 64 + h) * 64 + pb] = lo;
        if (oc + 1 < 27) {
            float b1 = b_off[oc + 1];
            float4 hi = make_float4(p0.y + b1, p1.y + b1, p2.y + b1, p3.y + b1);
            *(float4*)&g_om[((b * 27 + oc + 1) * 64 + h) * 64 + pb] = hi;
        }
    }
}

// ======== shared MMA blocks: per warp M32 x N32, A frags in regs, B via trans-ldsm ========
#define LDB(koff)                                                               \
    ldsm4t(bh0, bhB + boffT + (koff));                                          \
    ldsm4t(bh1, bhB + boffT + (koff) + 32);                                     \
    ldsm4t(bl0, blB + boffT + (koff));                                          \
    ldsm4t(bl1, blB + boffT + (koff) + 32);

#define MMA24(AH, AL)                                                           \
    {                                                                           \
        _Pragma("unroll")                                                       \
        for (int i = 0; i < 2; i++) {                                           \
            const u32* Ah = (const u32*)&AH[i];                                 \
            const u32* Al = (const u32*)&AL[i];                                 \
            mma16816(acc[i][0], Ah, bh0[0], bh0[1]);                            \
            mma16816(acc[i][1], Ah, bh0[2], bh0[3]);                            \
            mma16816(acc[i][2], Ah, bh1[0], bh1[1]);                            \
            mma16816(acc[i][3], Ah, bh1[2], bh1[3]);                            \
            mma16816(acc[i][0], Ah, bl0[0], bl0[1]);                            \
            mma16816(acc[i][1], Ah, bl0[2], bl0[3]);                            \
            mma16816(acc[i][2], Ah, bl1[0], bl1[1]);                            \
            mma16816(acc[i][3], Ah, bl1[2], bl1[3]);                            \
            mma16816(acc[i][0], Al, bh0[0], bh0[1]);                            \
            mma16816(acc[i][1], Al, bh0[2], bh0[3]);                            \
            mma16816(acc[i][2], Al, bh1[0], bh1[1]);                            \
            mma16816(acc[i][3], Al, bh1[2], bh1[3]);                            \
        }                                                                       \
    }

// ================= mdcn =================
#define MD_MW   0                    // metaW 576*16 = 9216
#define MD_MI   9216                 // metaI 576*4 = 2304
#define MD_BH0  11520                // B tiles: 32 x 144B = 4608 each
#define MD_BH1  16128
#define MD_BL0  20736
#define MD_BL1  25344
#define MD_SMEM 29952

__global__ void __launch_bounds__(256, 2)
mdcn_mma_kernel(const float* __restrict__ x, const float* __restrict__ b_dcn) {
    extern __shared__ char sm[];
    u32 sb = smem_u32(sm);
    int b = blockIdx.x >> 6;
    int h = blockIdx.x & 63;
    int t = threadIdx.x;
    int wid = t >> 5;
    int lane = t & 31;

    float4* metaW = (float4*)(sm + MD_MW);
    u32* metaI = (u32*)(sm + MD_MI);

    for (int e = t; e < 576; e += 256) {
        int pixl = e / 9;
        int k = e - pixl * 9;
        int w = pixl;
        const float* omb = g_om + (b * 27) * 4096 + h * 64 + w;
        float dy = omb[(2 * k) * 4096];
        float dx = omb[(2 * k + 1) * 4096];
        float mr = omb[(18 + k) * 4096];
        float m = 1.f / (1.f + expf(-mr));
        int ky = k / 3, kx = k - ky * 3;
        float ys = (float)(h - 1 + ky) + dy;
        float xs = (float)(w - 1 + kx) + dx;
        float y0f = floorf(ys), x0f = floorf(xs);
        float ly = ys - y0f, lx = xs - x0f;
        int y0 = (int)y0f, x0 = (int)x0f;
        int y1 = y0 + 1, x1 = x0 + 1;
        float vy0 = ((unsigned)y0 < 64u) ? 1.f : 0.f;
        float vy1 = ((unsigned)y1 < 64u) ? 1.f : 0.f;
        float vx0 = ((unsigned)x0 < 64u) ? 1.f : 0.f;
        float vx1 = ((unsigned)x1 < 64u) ? 1.f : 0.f;
        int iy0 = min(max(y0, 0), 63), iy1 = min(max(y1, 0), 63);
        int ix0 = min(max(x0, 0), 63), ix1 = min(max(x1, 0), 63);
        float4 wv;
        wv.x = (1.f - ly) * (1.f - lx) * m * vy0 * vx0;
        wv.y = (1.f - ly) * lx * m * vy0 * vx1;
        wv.z = ly * (1.f - lx) * m * vy1 * vx0;
        wv.w = ly * lx * m * vy1 * vx1;
        metaW[e] = wv;
        metaI[e] = (u32)iy0 | ((u32)iy1 << 8) | ((u32)ix0 << 16) | ((u32)ix1 << 24);
    }
    __syncthreads();

    int m0 = (wid >> 1) * 32;
    int n0w = (wid & 1) * 32;
    int mt0 = (wid >> 1) * 2;
    float acc[2][4][4];
#pragma unroll
    for (int i = 0; i < 2; i++)
#pragma unroll
        for (int j = 0; j < 4; j++)
#pragma unroll
            for (int q = 0; q < 4; q++) acc[i][j][q] = 0.f;

    const float* xb = x + b * 256 * 4096;
    const int bhOff[2] = {MD_BH0, MD_BH1};
    const int blOff[2] = {MD_BL0, MD_BL1};
    int px = t & 63;
    int q8 = (t >> 6) * 8;

    u32 boffT = (u32)((lane & 7) + ((lane >> 3) & 1) * 8) * PK + ((lane >> 4) & 1) * 16 + (u32)n0w * 2;

#define MD_LDA(dh, dl, c, ks)                                                   \
    {                                                                           \
        int base0 = ((((c) * 2 + (ks)) * 8 + mt0) * 32 + lane) * 16;            \
        dh[0] = __ldg((const uint4*)((const char*)g_wAH + base0));              \
        dh[1] = __ldg((const uint4*)((const char*)g_wAH + base0 + 512));        \
        dl[0] = __ldg((const uint4*)((const char*)g_wAL + base0));              \
        dl[1] = __ldg((const uint4*)((const char*)g_wAL + base0 + 512));        \
    }
#define MD_STOREB(c, dst)                                                       \
    {                                                                           \
        char* bhp = sm + bhOff[dst];                                            \
        char* blp = sm + blOff[dst];                                            \
        _Pragma("unroll")                                                       \
        for (int j = 0; j < 8; j++) {                                           \
            int kin = q8 + j;                                                   \
            int k = (c) * 32 + kin;                                             \
            int ci = k / 9;                                                     \
            int kk = k - 9 * ci;                                                \
            int mi = px * 9 + kk;                                               \
            u32 pk = metaI[mi];                                                 \
            float4 wv = metaW[mi];                                              \
            const float* xc = xb + (ci << 12);                                  \
            int iy0 = pk & 255, iy1 = (pk >> 8) & 255;                          \
            int ix0 = (pk >> 16) & 255, ix1 = pk >> 24;                         \
            float v = wv.x * xc[iy0 * 64 + ix0] + wv.y * xc[iy0 * 64 + ix1]     \
                    + wv.z * xc[iy1 * 64 + ix0] + wv.w * xc[iy1 * 64 + ix1];    \
            __nv_bfloat16 hv = __float2bfloat16(v);                             \
            float lv = v - __bfloat162float(hv);                                \
            int off = kin * PK + px * 2;                                        \
            *(__nv_bfloat16*)(bhp + off) = hv;                                  \
            *(__nv_bfloat16*)(blp + off) = __float2bfloat16(lv);                \
        }                                                                       \
    }

    uint4 a0h[2], a0l[2], a1h[2], a1l[2];
    u32 bh0[4], bh1[4], bl0[4], bl1[4];

    MD_STOREB(0, 0)
    __syncthreads();
    for (int c = 0; c < 72; c++) {
        int cur = c & 1;
        u32 bhB = sb + bhOff[cur], blB = sb + blOff[cur];
        MD_LDA(a0h, a0l, c, 0)
        MD_LDA(a1h, a1l, c, 1)
        LDB(0)
        MMA24(a0h, a0l)
        LDB(16 * PK)
        MMA24(a1h, a1l)
        if (c < 71) MD_STOREB(c + 1, cur ^ 1)
        __syncthreads();
    }

#pragma unroll
    for (int i = 0; i < 2; i++) {
        int r = m0 + i * 16 + (lane >> 2);
        float bb0 = b_dcn[r];
        float bb1 = b_dcn[r + 8];
#pragma unroll
        for (int nt = 0; nt < 4; nt++) {
            int nn = n0w + nt * 8 + 2 * (lane & 3);
            float* cp = acc[i][nt];
            *(float2*)&g_y[((b * 128 + r) << 12) + h * 64 + nn] = make_float2(cp[0] + bb0, cp[1] + bb0);
            *(float2*)&g_y[((b * 128 + r + 8) << 12) + h * 64 + nn] = make_float2(cp[2] + bb1, cp[3] + bb1);
        }
    }
}

// ---------------- BN stats ----------------
__global__ void __launch_bounds__(1024) bn_stats_kernel(const float* __restrict__ src, int shift,
                                                        const float* __restrict__ gamma,
                                                        const float* __restrict__ beta,
                                                        float* gs, float* gt) {
    int c = blockIdx.x;
    int t = threadIdx.x;
    float s = 0.f, q = 0.f;
    for (int i = t; i < (4 << (shift - 2)); i += 1024) {
        int bb = i >> (shift - 2);
        int r = i - (bb << (shift - 2));
        float4 v = ((const float4*)src)[(size_t)((bb * 128 + c) << (shift - 2)) + r];
        s += v.x + v.y + v.z + v.w;
        q += v.x * v.x + v.y * v.y + v.z * v.z + v.w * v.w;
    }
    __shared__ float rs[1024], rq[1024];
    rs[t] = s; rq[t] = q;
    __syncthreads();
    for (int o = 512; o > 0; o >>= 1) {
        if (t < o) { rs[t] += rs[t + o]; rq[t] += rq[t + o]; }
        __syncthreads();
    }
    if (t == 0) {
        float inv = 1.f / (float)(4 << shift);
        float mean = rs[0] * inv;
        float var = rq[0] * inv - mean * mean;
        float sc = gamma[c] * rsqrtf(var + 1e-5f);
        gs[c] = sc;
        gt[c] = beta[c] - mean * sc;
    }
}

// ================= deconv =================
#define DC_BN   0                    // bn1 cache: 2 x 128 floats = 1024
#define DC_BH0  1024
#define DC_BH1  5632
#define DC_BL0  10240
#define DC_BL1  14848
#define DC_SMEM 19456

__global__ void __launch_bounds__(256, 2)
deconv_mma_kernel() {
    extern __shared__ char sm[];
    u32 sb = smem_u32(sm);
    int b = blockIdx.x >> 8;
    int rem = blockIdx.x & 255;
    int Y = rem >> 1;
    int pX = rem & 1;
    int p = ((Y & 1) << 1) | pX;
    int t = threadIdx.x;
    int wid = t >> 5;
    int lane = t & 31;

    float* bnS = (float*)(sm + DC_BN);
    float* bnT = (float*)(sm + DC_BN + 512);
    if (t < 128) { bnS[t] = g_bn1s[t]; bnT[t] = g_bn1t[t]; }

    int m0 = (wid >> 1) * 32;
    int n0w = (wid & 1) * 32;
    int mt0 = (wid >> 1) * 2;
    float acc[2][4][4];
#pragma unroll
    for (int i = 0; i < 2; i++)
#pragma unroll
        for (int j = 0; j < 4; j++)
#pragma unroll
            for (int q = 0; q < 4; q++) acc[i][j][q] = 0.f;

    const float* yb = g_y + b * 128 * 4096;
    const int bhOff[2] = {DC_BH0, DC_BH1};
    const int blOff[2] = {DC_BL0, DC_BL1};
    int px = t & 63;
    int q8 = (t >> 6) * 8;

    u32 boffT = (u32)((lane & 7) + ((lane >> 3) & 1) * 8) * PK + ((lane >> 4) & 1) * 16 + (u32)n0w * 2;

#define DC_LDA(dh, dl, c, ks)                                                   \
    {                                                                           \
        int base0 = ((((p * 16 + (c)) * 2 + (ks)) * 8 + mt0) * 32 + lane) * 16; \
        dh[0] = __ldg((const uint4*)((const char*)g_wuH + base0));              \
        dh[1] = __ldg((const uint4*)((const char*)g_wuH + base0 + 512));        \
        dl[0] = __ldg((const uint4*)((const char*)g_wuL + base0));              \
        dl[1] = __ldg((const uint4*)((const char*)g_wuL + base0 + 512));        \
    }
#define DC_STOREB(c, dst)                                                       \
    {                                                                           \
        char* bhp = sm + bhOff[dst];                                            \
        char* blp = sm + blOff[dst];                                            \
        _Pragma("unroll")                                                       \
        for (int j = 0; j < 8; j++) {                                           \
            int kin = q8 + j;                                                   \
            int k = (c) * 32 + kin;                                             \
            int cc2 = k >> 2;                                                   \
            int tap = k & 3;                                                    \
            int ky = ((Y & 1) ^ 1) + 2 * (tap >> 1);                            \
            int hh = (Y + 1 - ky) >> 1;                                         \
            int kx = (pX ^ 1) + 2 * (tap & 1);                                  \
            int ww = px + ((pX + 1 - kx) >> 1);                                 \
            float v = 0.f;                                                      \
            if ((unsigned)hh < 64u && (unsigned)ww < 64u) {                     \
                float yv = yb[(cc2 << 12) + hh * 64 + ww];                      \
                v = fmaxf(yv * bnS[cc2] + bnT[cc2], 0.f);                       \
            }                                                                   \
            __nv_bfloat16 hv = __float2bfloat16(v);                             \
            float lv = v - __bfloat162float(hv);                                \
            int off = kin * PK + px * 2;                                        \
            *(__nv_bfloat16*)(bhp + off) = hv;                                  \
            *(__nv_bfloat16*)(blp + off) = __float2bfloat16(lv);                \
        }                                                                       \
    }

    uint4 a0h[2], a0l[2], a1h[2], a1l[2];
    u32 bh0[4], bh1[4], bl0[4], bl1[4];

    __syncthreads();   // bn cache visible before producers read it
    DC_STOREB(0, 0)
    __syncthreads();
    for (int c = 0; c < 16; c++) {
        int cur = c & 1;
        u32 bhB = sb + bhOff[cur], blB = sb + blOff[cur];
        DC_LDA(a0h, a0l, c, 0)
        DC_LDA(a1h, a1l, c, 1)
        LDB(0)
        MMA24(a0h, a0l)
        LDB(16 * PK)
        MMA24(a1h, a1l)
        if (c < 15) DC_STOREB(c + 1, cur ^ 1)
        __syncthreads();
    }

#pragma unroll
    for (int i = 0; i < 2; i++) {
        int r = m0 + i * 16 + (lane >> 2);
#pragma unroll
        for (int nt = 0; nt < 4; nt++) {
            int nn = n0w + nt * 8 + 2 * (lane & 3);
            float* cp = acc[i][nt];
            size_t base0 = (size_t)((b * 128 + r) * 128 + Y) * 128 + pX * 64 + nn;
            size_t base1 = (size_t)((b * 128 + r + 8) * 128 + Y) * 128 + pX * 64 + nn;
            *(float2*)&g_up[base0] = make_float2(cp[0], cp[1]);
            *(float2*)&g_up[base1] = make_float2(cp[2], cp[3]);
        }
    }
}

// ---------------- BN2 + ReLU + parity de-interleave ----------------
__global__ void __launch_bounds__(256) final_kernel(float* __restrict__ out) {
    __shared__ float s[8][128];
    int row0 = blockIdx.x * 8;
    int r = threadIdx.x >> 5;
    int q = threadIdx.x & 31;
    int grow = row0 + r;
    ((float4*)s[r])[q] = ((const float4*)g_up)[grow * 32 + q];
    __syncthreads();
    int bo = grow >> 7;
    int oc = bo & 127;
    float sc = g_bn2s[oc], sh = g_bn2t[oc];
    float v0 = s[r][q * 2];
    float v1 = s[r][64 + q * 2];
    float v2 = s[r][q * 2 + 1];
    float v3 = s[r][64 + q * 2 + 1];
    float4 o4 = make_float4(fmaxf(v0 * sc + sh, 0.f), fmaxf(v1 * sc + sh, 0.f),
                            fmaxf(v2 * sc + sh, 0.f), fmaxf(v3 * sc + sh, 0.f));
    *(float4*)&out[grow * 128 + q * 4] = o4;
}

// ---------------- launch ----------------
extern "C" void kernel_launch(void* const* d_in, const int* in_sizes, int n_in,
                              void* d_out, int out_size) {
    const float* x      = (const float*)d_in[0];
    const float* w_off  = (const float*)d_in[1];
    const float* b_off  = (const float*)d_in[2];
    const float* w_dcn  = (const float*)d_in[3];
    const float* b_dcn  = (const float*)d_in[4];
    const float* gamma1 = (const float*)d_in[5];
    const float* beta1  = (const float*)d_in[6];
    const float* w_up   = (const float*)d_in[7];
    const float* gamma2 = (const float*)d_in[8];
    const float* beta2  = (const float*)d_in[9];

    (void)cudaFuncSetAttribute(mdcn_mma_kernel, cudaFuncAttributeMaxDynamicSharedMemorySize, MD_SMEM);
    (void)cudaFuncSetAttribute(deconv_mma_kernel, cudaFuncAttributeMaxDynamicSharedMemorySize, DC_SMEM);

    float* yptr;  cudaGetSymbolAddress((void**)&yptr, g_y);
    float* uptr;  cudaGetSymbolAddress((void**)&uptr, g_up);
    float* b1s;   cudaGetSymbolAddress((void**)&b1s, g_bn1s);
    float* b1t;   cudaGetSymbolAddress((void**)&b1t, g_bn1t);
    float* b2s;   cudaGetSymbolAddress((void**)&b2s, g_bn2s);
    float* b2t;   cudaGetSymbolAddress((void**)&b2t, g_bn2t);

    int prepN = 72 * 4096 + 4 * 16 * 4096 + 2304 * 32;
    prep_weights<<<(prepN + 255) / 256, 256>>>(w_off, w_dcn, w_up);   // idx 0
    conv_off_kernel<<<NB * 64, 256>>>(x, b_off);                      // idx 1
    dummy_kernel<<<1, 32>>>();                                        // idx 2
    mdcn_mma_kernel<<<NB * 64, 256, MD_SMEM>>>(x, b_dcn);             // idx 3 (ncu slot)
    bn_stats_kernel<<<128, 1024>>>(yptr, 12, gamma1, beta1, b1s, b1t);
    deconv_mma_kernel<<<NB * 256, 256, DC_SMEM>>>();
    bn_stats_kernel<<<128, 1024>>>(uptr, 14, gamma2, beta2, b2s, b2t);
    final_kernel<<<(NB * 128 * 128 * 128) / 1024, 256>>>((float*)d_out);
}

// round 16
// speedup vs baseline: 1.0941x; 1.0941x over previous
#include <cuda_runtime.h>
#include <cuda_bf16.h>
#include <cstdint>

#define NB 4
typedef unsigned long long ull;
typedef unsigned int u32;

// ---------------- scratch ----------------
__device__ float g_om[NB * 27 * 64 * 64];
__device__ float g_y[NB * 128 * 64 * 64];
__device__ float g_up[NB * 128 * 128 * 128];
__device__ float g_woffT[2304 * 32];
__device__ __nv_bfloat16 g_wAH[72 * 4096];     // mdcn A frags hi  [chunk][ks][mt][lane][w][e]
__device__ __nv_bfloat16 g_wAL[72 * 4096];
__device__ __nv_bfloat16 g_wuH[4 * 16 * 4096]; // deconv A frags hi [p][chunk][ks][mt][lane][w][e]
__device__ __nv_bfloat16 g_wuL[4 * 16 * 4096];
__device__ float g_bn1s[128], g_bn1t[128];
__device__ float g_bn2s[128], g_bn2t[128];

// ---------------- helpers ----------------
__device__ __forceinline__ ull dup2(float v) {
    ull r; asm("mov.b64 %0, {%1,%1};" : "=l"(r) : "f"(v)); return r;
}
__device__ __forceinline__ void fma2(ull& d, ull a, ull b) {
    asm("fma.rn.f32x2 %0, %1, %2, %0;" : "+l"(d) : "l"(a), "l"(b));
}
__device__ __forceinline__ float2 unpk(ull v) {
    float2 r; asm("mov.b64 {%0, %1}, %2;" : "=f"(r.x), "=f"(r.y) : "l"(v)); return r;
}
__device__ __forceinline__ void cp16(void* s, const void* g) {
    unsigned sa = (unsigned)__cvta_generic_to_shared(s);
    asm volatile("cp.async.ca.shared.global [%0], [%1], 16;" :: "r"(sa), "l"(g));
}
__device__ __forceinline__ void cp_commit() { asm volatile("cp.async.commit_group;"); }
__device__ __forceinline__ void cp_wait0()  { asm volatile("cp.async.wait_group 0;" ::: "memory"); }

__device__ __forceinline__ u32 smem_u32(const void* p) {
    u32 a; asm("{ .reg .u64 t; cvta.to.shared.u64 t, %1; cvt.u32.u64 %0, t; }" : "=r"(a) : "l"(p));
    return a;
}
__device__ __forceinline__ void ldsm4t(u32* r, u32 addr) {
    asm volatile("ldmatrix.sync.aligned.m8n8.x4.trans.shared.b16 {%0,%1,%2,%3}, [%4];"
                 : "=r"(r[0]), "=r"(r[1]), "=r"(r[2]), "=r"(r[3]) : "r"(addr));
}
__device__ __forceinline__ void mma16816(float* c, const u32* a, u32 b0, u32 b1) {
    asm volatile(
        "mma.sync.aligned.m16n8k16.row.col.f32.bf16.bf16.f32 "
        "{%0,%1,%2,%3}, {%4,%5,%6,%7}, {%8,%9}, {%0,%1,%2,%3};"
        : "+f"(c[0]), "+f"(c[1]), "+f"(c[2]), "+f"(c[3])
        : "r"(a[0]), "r"(a[1]), "r"(a[2]), "r"(a[3]), "r"(b0), "r"(b1));
}

// B tile: [k32][n64], row = 64 bf16 = 128B + 16B pad = 144B pitch
#define PK 144

// ---------------- kernel 0: weights in MMA-fragment order + hi/lo split ----------------
__global__ void __launch_bounds__(256) prep_weights(const float* __restrict__ w_off,
                                                    const float* __restrict__ w_dcn,
                                                    const float* __restrict__ w_up) {
    int idx = blockIdx.x * 256 + threadIdx.x;
    const int NW1 = 72 * 4096;
    const int NW2 = 4 * 16 * 4096;
    if (idx < NW1) {
        int e = idx & 1, w = (idx >> 1) & 3, lane = (idx >> 3) & 31;
        int mt = (idx >> 8) & 7, ks = (idx >> 11) & 1, chunk = idx >> 12;
        int oc = mt * 16 + (w & 1) * 8 + (lane >> 2);
        int k  = chunk * 32 + ks * 16 + (w >> 1) * 8 + (lane & 3) * 2 + e;
        float v = w_dcn[oc * 2304 + k];
        __nv_bfloat16 hi = __float2bfloat16(v);
        __nv_bfloat16 lo = __float2bfloat16(v - __bfloat162float(hi));
        g_wAH[idx] = hi;
        g_wAL[idx] = lo;
        return;
    }
    int i2 = idx - NW1;
    if (i2 < NW2) {
        int e = i2 & 1, w = (i2 >> 1) & 3, lane = (i2 >> 3) & 31;
        int mt = (i2 >> 8) & 7, ks = (i2 >> 11) & 1, chunk = (i2 >> 12) & 15;
        int p = i2 >> 16;
        int oc = mt * 16 + (w & 1) * 8 + (lane >> 2);
        int k  = chunk * 32 + ks * 16 + (w >> 1) * 8 + (lane & 3) * 2 + e;
        int c = k >> 2, tap = k & 3;
        int ty = tap >> 1, tx = tap & 1;
        int pY = p >> 1, pX = p & 1;
        int ky = (pY ^ 1) + 2 * ty;
        int kx = (pX ^ 1) + 2 * tx;
        float v = w_up[((c * 128 + oc) * 4 + ky) * 4 + kx];
        __nv_bfloat16 hi = __float2bfloat16(v);
        __nv_bfloat16 lo = __float2bfloat16(v - __bfloat162float(hi));
        g_wuH[i2] = hi;
        g_wuL[i2] = lo;
        return;
    }
    int i3 = i2 - NW2;
    if (i3 < 2304 * 32) {
        int ck = i3 >> 5, oc = i3 & 31;
        g_woffT[i3] = (oc < 27) ? w_off[oc * 2304 + ck] : 0.f;
    }
}

// ---------------- dummy (ncu capture = idx 3) ----------------
__global__ void dummy_kernel() {}

// ---------------- kernel 1: 3x3 offset conv (SIMT fma2, unchanged) ------------
__global__ void __launch_bounds__(256, 2) conv_off_kernel(const float* __restrict__ x,
                                                          const float* __restrict__ b_off) {
    __shared__ float As[2][36][32];
    __shared__ float Bs[2][36][64];
    int b = blockIdx.x >> 6;
    int h = blockIdx.x & 63;
    int t = threadIdx.x;
    int ocp = t >> 4;
    int pb = (t & 15) << 2;
    const float* xb = x + b * 256 * 4096;
    ull acc[4];
#pragma unroll
    for (int j = 0; j < 4; j++) acc[j] = 0ull;
    float xv[9];

#define COFF_LOADB(c0)                                                          \
    {                                                                           \
        _Pragma("unroll")                                                       \
        for (int i = 0; i < 9; i++) {                                           \
            int e = t + (i << 8);                                               \
            int kc = e >> 6, wx = e & 63;                                       \
            int ci = kc / 9, kk = kc - ci * 9;                                  \
            int ky = kk / 3, kx = kk - ky * 3;                                  \
            int yy = h + ky - 1, xx = wx + kx - 1;                              \
            float v = 0.f;                                                      \
            if ((unsigned)yy < 64u && (unsigned)xx < 64u)                       \
                v = xb[((c0) + ci) * 4096 + yy * 64 + xx];                      \
            xv[i] = v;                                                          \
        }                                                                       \
    }
#define COFF_STOREB(dst)                                                        \
    {                                                                           \
        _Pragma("unroll")                                                       \
        for (int i = 0; i < 9; i++) {                                           \
            int e = t + (i << 8);                                               \
            int kc = e >> 6, wx = e & 63;                                       \
            Bs[dst][kc][wx] = xv[i];                                            \
        }                                                                       \
    }
#define COFF_LOADA(c0, dst)                                                     \
    {                                                                           \
        const float4* wsrc = (const float4*)(g_woffT + (c0) * 9 * 32);          \
        _Pragma("unroll")                                                       \
        for (int i = 0; i < 2; i++) {                                           \
            int e = t + (i << 8);                                               \
            if (e < 288) cp16(&((float4*)As[dst])[e], wsrc + e);                \
        }                                                                       \
        cp_commit();                                                            \
    }
#define COFF_COMPUTE(cc)                                                        \
    {                                                                           \
        _Pragma("unroll")                                                       \
        for (int kc = 0; kc < 36; kc++) {                                       \
            ull Au = *(const ull*)&As[cc][kc][ocp * 2];                         \
            float4 bv = *(const float4*)&Bs[cc][kc][pb];                        \
            fma2(acc[0], Au, dup2(bv.x));                                       \
            fma2(acc[1], Au, dup2(bv.y));                                       \
            fma2(acc[2], Au, dup2(bv.z));                                       \
            fma2(acc[3], Au, dup2(bv.w));                                       \
        }                                                                       \
    }

    int cur = 0;
    COFF_LOADA(0, 0)
    COFF_LOADB(0)
    COFF_STOREB(0)
    cp_wait0();
    __syncthreads();
    for (int c0 = 4; c0 < 256; c0 += 4) {
        int nxt = cur ^ 1;
        COFF_LOADA(c0, nxt)
        COFF_LOADB(c0)
        COFF_COMPUTE(cur)
        COFF_STOREB(nxt)
        cp_wait0();
        __syncthreads();
        cur = nxt;
    }
    COFF_COMPUTE(cur)

    int oc = 2 * ocp;
    if (oc < 27) {
        float2 p0 = unpk(acc[0]), p1 = unpk(acc[1]), p2 = unpk(acc[2]), p3 = unpk(acc[3]);
        float bo = b_off[oc];
        float4 lo = make_float4(p0.x + bo, p1.x + bo, p2.x + bo, p3.x + bo);
        *(float4*)&g_om[((b * 27 + oc) * 64 + h) * 64 + pb] = lo;
        if (oc + 1 < 27) {
            float b1 = b_off[oc + 1];
            float4 hi = make_float4(p0.y + b1, p1.y + b1, p2.y + b1, p3.y + b1);
            *(float4*)&g_om[((b * 27 + oc + 1) * 64 + h) * 64 + pb] = hi;
        }
    }
}

// ======== shared MMA blocks: per warp M32 x N32, A frags in regs, B via trans-ldsm ========
#define LDB(koff)                                                               \
    ldsm4t(bh0, bhB + boffT + (koff));                                          \
    ldsm4t(bh1, bhB + boffT + (koff) + 32);                                     \
    ldsm4t(bl0, blB + boffT + (koff));                                          \
    ldsm4t(bl1, blB + boffT + (koff) + 32);

#define MMA24(AH, AL)                                                           \
    {                                                                           \
        _Pragma("unroll")                                                       \
        for (int i = 0; i < 2; i++) {                                           \
            const u32* Ah = (const u32*)&AH[i];                                 \
            const u32* Al = (const u32*)&AL[i];                                 \
            mma16816(acc[i][0], Ah, bh0[0], bh0[1]);                            \
            mma16816(acc[i][1], Ah, bh0[2], bh0[3]);                            \
            mma16816(acc[i][2], Ah, bh1[0], bh1[1]);                            \
            mma16816(acc[i][3], Ah, bh1[2], bh1[3]);                            \
            mma16816(acc[i][0], Ah, bl0[0], bl0[1]);                            \
            mma16816(acc[i][1], Ah, bl0[2], bl0[3]);                            \
            mma16816(acc[i][2], Ah, bl1[0], bl1[1]);                            \
            mma16816(acc[i][3], Ah, bl1[2], bl1[3]);                            \
            mma16816(acc[i][0], Al, bh0[0], bh0[1]);                            \
            mma16816(acc[i][1], Al, bh0[2], bh0[3]);                            \
            mma16816(acc[i][2], Al, bh1[0], bh1[1]);                            \
            mma16816(acc[i][3], Al, bh1[2], bh1[3]);                            \
        }                                                                       \
    }

// ================= mdcn (4-slot B ring, 1 barrier / 2 chunks, 3 CTA/SM) =================
#define MD_MW   0                    // metaW 576*16 = 9216
#define MD_MI   9216                 // metaI 576*4 = 2304
#define MD_BH(i) (11520 + (i) * 4608)
#define MD_BL(i) (29952 + (i) * 4608)
#define MD_SMEM 48384

__global__ void __launch_bounds__(256, 3)
mdcn_mma_kernel(const float* __restrict__ x, const float* __restrict__ b_dcn) {
    extern __shared__ char sm[];
    u32 sb = smem_u32(sm);
    int b = blockIdx.x >> 6;
    int h = blockIdx.x & 63;
    int t = threadIdx.x;
    int wid = t >> 5;
    int lane = t & 31;

    float4* metaW = (float4*)(sm + MD_MW);
    u32* metaI = (u32*)(sm + MD_MI);

    for (int e = t; e < 576; e += 256) {
        int pixl = e / 9;
        int k = e - pixl * 9;
        int w = pixl;
        const float* omb = g_om + (b * 27) * 4096 + h * 64 + w;
        float dy = omb[(2 * k) * 4096];
        float dx = omb[(2 * k + 1) * 4096];
        float mr = omb[(18 + k) * 4096];
        float m = 1.f / (1.f + expf(-mr));
        int ky = k / 3, kx = k - ky * 3;
        float ys = (float)(h - 1 + ky) + dy;
        float xs = (float)(w - 1 + kx) + dx;
        float y0f = floorf(ys), x0f = floorf(xs);
        float ly = ys - y0f, lx = xs - x0f;
        int y0 = (int)y0f, x0 = (int)x0f;
        int y1 = y0 + 1, x1 = x0 + 1;
        float vy0 = ((unsigned)y0 < 64u) ? 1.f : 0.f;
        float vy1 = ((unsigned)y1 < 64u) ? 1.f : 0.f;
        float vx0 = ((unsigned)x0 < 64u) ? 1.f : 0.f;
        float vx1 = ((unsigned)x1 < 64u) ? 1.f : 0.f;
        int iy0 = min(max(y0, 0), 63), iy1 = min(max(y1, 0), 63);
        int ix0 = min(max(x0, 0), 63), ix1 = min(max(x1, 0), 63);
        float4 wv;
        wv.x = (1.f - ly) * (1.f - lx) * m * vy0 * vx0;
        wv.y = (1.f - ly) * lx * m * vy0 * vx1;
        wv.z = ly * (1.f - lx) * m * vy1 * vx0;
        wv.w = ly * lx * m * vy1 * vx1;
        metaW[e] = wv;
        metaI[e] = (u32)iy0 | ((u32)iy1 << 8) | ((u32)ix0 << 16) | ((u32)ix1 << 24);
    }
    __syncthreads();

    int m0 = (wid >> 1) * 32;
    int n0w = (wid & 1) * 32;
    int mt0 = (wid >> 1) * 2;
    float acc[2][4][4];
#pragma unroll
    for (int i = 0; i < 2; i++)
#pragma unroll
        for (int j = 0; j < 4; j++)
#pragma unroll
            for (int q = 0; q < 4; q++) acc[i][j][q] = 0.f;

    const float* xb = x + b * 256 * 4096;
    int px = t & 63;
    int q8 = (t >> 6) * 8;

    u32 boffT = (u32)((lane & 7) + ((lane >> 3) & 1) * 8) * PK + ((lane >> 4) & 1) * 16 + (u32)n0w * 2;

#define MD_LDA(dh, dl, c, ks)                                                   \
    {                                                                           \
        int base0 = ((((c) * 2 + (ks)) * 8 + mt0) * 32 + lane) * 16;            \
        dh[0] = __ldg((const uint4*)((const char*)g_wAH + base0));              \
        dh[1] = __ldg((const uint4*)((const char*)g_wAH + base0 + 512));        \
        dl[0] = __ldg((const uint4*)((const char*)g_wAL + base0));              \
        dl[1] = __ldg((const uint4*)((const char*)g_wAL + base0 + 512));        \
    }
#define MD_STOREB(c, slot)                                                      \
    {                                                                           \
        char* bhp = sm + MD_BH(slot);                                           \
        char* blp = sm + MD_BL(slot);                                           \
        _Pragma("unroll")                                                       \
        for (int j = 0; j < 8; j++) {                                           \
            int kin = q8 + j;                                                   \
            int k = (c) * 32 + kin;                                             \
            int ci = k / 9;                                                     \
            int kk = k - 9 * ci;                                                \
            int mi = px * 9 + kk;                                               \
            u32 pk = metaI[mi];                                                 \
            float4 wv = metaW[mi];                                              \
            const float* xc = xb + (ci << 12);                                  \
            int iy0 = pk & 255, iy1 = (pk >> 8) & 255;                          \
            int ix0 = (pk >> 16) & 255, ix1 = pk >> 24;                         \
            float v = wv.x * xc[iy0 * 64 + ix0] + wv.y * xc[iy0 * 64 + ix1]     \
                    + wv.z * xc[iy1 * 64 + ix0] + wv.w * xc[iy1 * 64 + ix1];    \
            __nv_bfloat16 hv = __float2bfloat16(v);                             \
            float lv = v - __bfloat162float(hv);                                \
            int off = kin * PK + px * 2;                                        \
            *(__nv_bfloat16*)(bhp + off) = hv;                                  \
            *(__nv_bfloat16*)(blp + off) = __float2bfloat16(lv);                \
        }                                                                       \
    }
#define MD_CHUNK(c, slot)                                                       \
    {                                                                           \
        u32 bhB = sb + MD_BH(slot), blB = sb + MD_BL(slot);                     \
        MD_LDA(ah, al, c, 0)                                                    \
        LDB(0)                                                                  \
        MMA24(ah, al)                                                           \
        MD_LDA(ah, al, c, 1)                                                    \
        LDB(16 * PK)                                                            \
        MMA24(ah, al)                                                           \
    }

    uint4 ah[2], al[2];
    u32 bh0[4], bh1[4], bl0[4], bl1[4];

    MD_STOREB(0, 0)
    MD_STOREB(1, 1)
    __syncthreads();
    for (int cp = 0; cp < 36; cp++) {
        int c0 = 2 * cp;
        MD_CHUNK(c0, c0 & 3)
        MD_CHUNK(c0 + 1, (c0 + 1) & 3)
        if (cp < 35) {
            MD_STOREB(c0 + 2, (c0 + 2) & 3)
            MD_STOREB(c0 + 3, (c0 + 3) & 3)
        }
        __syncthreads();
    }

#pragma unroll
    for (int i = 0; i < 2; i++) {
        int r = m0 + i * 16 + (lane >> 2);
        float bb0 = b_dcn[r];
        float bb1 = b_dcn[r + 8];
#pragma unroll
        for (int nt = 0; nt < 4; nt++) {
            int nn = n0w + nt * 8 + 2 * (lane & 3);
            float* cp2 = acc[i][nt];
            *(float2*)&g_y[((b * 128 + r) << 12) + h * 64 + nn] = make_float2(cp2[0] + bb0, cp2[1] + bb0);
            *(float2*)&g_y[((b * 128 + r + 8) << 12) + h * 64 + nn] = make_float2(cp2[2] + bb1, cp2[3] + bb1);
        }
    }
}

// ---------------- BN stats ----------------
__global__ void __launch_bounds__(1024) bn_stats_kernel(const float* __restrict__ src, int shift,
                                                        const float* __restrict__ gamma,
                                                        const float* __restrict__ beta,
                                                        float* gs, float* gt) {
    int c = blockIdx.x;
    int t = threadIdx.x;
    float s = 0.f, q = 0.f;
    for (int i = t; i < (4 << (shift - 2)); i += 1024) {
        int bb = i >> (shift - 2);
        int r = i - (bb << (shift - 2));
        float4 v = ((const float4*)src)[(size_t)((bb * 128 + c) << (shift - 2)) + r];
        s += v.x + v.y + v.z + v.w;
        q += v.x * v.x + v.y * v.y + v.z * v.z + v.w * v.w;
    }
    __shared__ float rs[1024], rq[1024];
    rs[t] = s; rq[t] = q;
    __syncthreads();
    for (int o = 512; o > 0; o >>= 1) {
        if (t < o) { rs[t] += rs[t + o]; rq[t] += rq[t + o]; }
        __syncthreads();
    }
    if (t == 0) {
        float inv = 1.f / (float)(4 << shift);
        float mean = rs[0] * inv;
        float var = rq[0] * inv - mean * mean;
        float sc = gamma[c] * rsqrtf(var + 1e-5f);
        gs[c] = sc;
        gt[c] = beta[c] - mean * sc;
    }
}

// ================= deconv (4-slot ring, 1 barrier / 2 chunks, 3 CTA/SM) =================
#define DC_BN   0                    // bn1 cache: 2 x 128 floats = 1024
#define DC_BH(i) (1024 + (i) * 4608)
#define DC_BL(i) (19456 + (i) * 4608)
#define DC_SMEM 37888

__global__ void __launch_bounds__(256, 3)
deconv_mma_kernel() {
    extern __shared__ char sm[];
    u32 sb = smem_u32(sm);
    int b = blockIdx.x >> 8;
    int rem = blockIdx.x & 255;
    int Y = rem >> 1;
    int pX = rem & 1;
    int p = ((Y & 1) << 1) | pX;
    int t = threadIdx.x;
    int wid = t >> 5;
    int lane = t & 31;

    float* bnS = (float*)(sm + DC_BN);
    float* bnT = (float*)(sm + DC_BN + 512);
    if (t < 128) { bnS[t] = g_bn1s[t]; bnT[t] = g_bn1t[t]; }

    int m0 = (wid >> 1) * 32;
    int n0w = (wid & 1) * 32;
    int mt0 = (wid >> 1) * 2;
    float acc[2][4][4];
#pragma unroll
    for (int i = 0; i < 2; i++)
#pragma unroll
        for (int j = 0; j < 4; j++)
#pragma unroll
            for (int q = 0; q < 4; q++) acc[i][j][q] = 0.f;

    const float* yb = g_y + b * 128 * 4096;
    int px = t & 63;
    int q8 = (t >> 6) * 8;

    u32 boffT = (u32)((lane & 7) + ((lane >> 3) & 1) * 8) * PK + ((lane >> 4) & 1) * 16 + (u32)n0w * 2;

#define DC_LDA(dh, dl, c, ks)                                                   \
    {                                                                           \
        int base0 = ((((p * 16 + (c)) * 2 + (ks)) * 8 + mt0) * 32 + lane) * 16; \
        dh[0] = __ldg((const uint4*)((const char*)g_wuH + base0));              \
        dh[1] = __ldg((const uint4*)((const char*)g_wuH + base0 + 512));        \
        dl[0] = __ldg((const uint4*)((const char*)g_wuL + base0));              \
        dl[1] = __ldg((const uint4*)((const char*)g_wuL + base0 + 512));        \
    }
#define DC_STOREB(c, slot)                                                      \
    {                                                                           \
        char* bhp = sm + DC_BH(slot);                                           \
        char* blp = sm + DC_BL(slot);                                           \
        _Pragma("unroll")                                                       \
        for (int j = 0; j < 8; j++) {                                           \
            int kin = q8 + j;                                                   \
            int k = (c) * 32 + kin;                                             \
            int cc2 = k >> 2;                                                   \
            int tap = k & 3;                                                    \
            int ky = ((Y & 1) ^ 1) + 2 * (tap >> 1);                            \
            int hh = (Y + 1 - ky) >> 1;                                         \
            int kx = (pX ^ 1) + 2 * (tap & 1);                                  \
            int ww = px + ((pX + 1 - kx) >> 1);                                 \
            float v = 0.f;                                                      \
            if ((unsigned)hh < 64u && (unsigned)ww < 64u) {                     \
                float yv = yb[(cc2 << 12) + hh * 64 + ww];                      \
                v = fmaxf(yv * bnS[cc2] + bnT[cc2], 0.f);                       \
            }                                                                   \
            __nv_bfloat16 hv = __float2bfloat16(v);                             \
            float lv = v - __bfloat162float(hv);                                \
            int off = kin * PK + px * 2;                                        \
            *(__nv_bfloat16*)(bhp + off) = hv;                                  \
            *(__nv_bfloat16*)(blp + off) = __float2bfloat16(lv);                \
        }                                                                       \
    }
#define DC_CHUNK(c, slot)                                                       \
    {                                                                           \
        u32 bhB = sb + DC_BH(slot), blB = sb + DC_BL(slot);                     \
        DC_LDA(ah, al, c, 0)                                                    \
        LDB(0)                                                                  \
        MMA24(ah, al)                                                           \
        DC_LDA(ah, al, c, 1)                                                    \
        LDB(16 * PK)                                                            \
        MMA24(ah, al)                                                           \
    }

    uint4 ah[2], al[2];
    u32 bh0[4], bh1[4], bl0[4], bl1[4];

    __syncthreads();   // bn cache visible
    DC_STOREB(0, 0)
    DC_STOREB(1, 1)
    __syncthreads();
    for (int cp = 0; cp < 8; cp++) {
        int c0 = 2 * cp;
        DC_CHUNK(c0, c0 & 3)
        DC_CHUNK(c0 + 1, (c0 + 1) & 3)
        if (cp < 7) {
            DC_STOREB(c0 + 2, (c0 + 2) & 3)
            DC_STOREB(c0 + 3, (c0 + 3) & 3)
        }
        __syncthreads();
    }

#pragma unroll
    for (int i = 0; i < 2; i++) {
        int r = m0 + i * 16 + (lane >> 2);
#pragma unroll
        for (int nt = 0; nt < 4; nt++) {
            int nn = n0w + nt * 8 + 2 * (lane & 3);
            float* cp2 = acc[i][nt];
            size_t base0 = (size_t)((b * 128 + r) * 128 + Y) * 128 + pX * 64 + nn;
            size_t base1 = (size_t)((b * 128 + r + 8) * 128 + Y) * 128 + pX * 64 + nn;
            *(float2*)&g_up[base0] = make_float2(cp2[0], cp2[1]);
            *(float2*)&g_up[base1] = make_float2(cp2[2], cp2[3]);
        }
    }
}

// ---------------- BN2 + ReLU + parity de-interleave ----------------
__global__ void __launch_bounds__(256) final_kernel(float* __restrict__ out) {
    __shared__ float s[8][128];
    int row0 = blockIdx.x * 8;
    int r = threadIdx.x >> 5;
    int q = threadIdx.x & 31;
    int grow = row0 + r;
    ((float4*)s[r])[q] = ((const float4*)g_up)[grow * 32 + q];
    __syncthreads();
    int bo = grow >> 7;
    int oc = bo & 127;
    float sc = g_bn2s[oc], sh = g_bn2t[oc];
    float v0 = s[r][q * 2];
    float v1 = s[r][64 + q * 2];
    float v2 = s[r][q * 2 + 1];
    float v3 = s[r][64 + q * 2 + 1];
    float4 o4 = make_float4(fmaxf(v0 * sc + sh, 0.f), fmaxf(v1 * sc + sh, 0.f),
                            fmaxf(v2 * sc + sh, 0.f), fmaxf(v3 * sc + sh, 0.f));
    *(float4*)&out[grow * 128 + q * 4] = o4;
}

// ---------------- launch ----------------
extern "C" void kernel_launch(void* const* d_in, const int* in_sizes, int n_in,
                              void* d_out, int out_size) {
    const float* x      = (const float*)d_in[0];
    const float* w_off  = (const float*)d_in[1];
    const float* b_off  = (const float*)d_in[2];
    const float* w_dcn  = (const float*)d_in[3];
    const float* b_dcn  = (const float*)d_in[4];
    const float* gamma1 = (const float*)d_in[5];
    const float* beta1  = (const float*)d_in[6];
    const float* w_up   = (const float*)d_in[7];
    const float* gamma2 = (const float*)d_in[8];
    const float* beta2  = (const float*)d_in[9];

    (void)cudaFuncSetAttribute(mdcn_mma_kernel, cudaFuncAttributeMaxDynamicSharedMemorySize, MD_SMEM);
    (void)cudaFuncSetAttribute(deconv_mma_kernel, cudaFuncAttributeMaxDynamicSharedMemorySize, DC_SMEM);

    float* yptr;  cudaGetSymbolAddress((void**)&yptr, g_y);
    float* uptr;  cudaGetSymbolAddress((void**)&uptr, g_up);
    float* b1s;   cudaGetSymbolAddress((void**)&b1s, g_bn1s);
    float* b1t;   cudaGetSymbolAddress((void**)&b1t, g_bn1t);
    float* b2s;   cudaGetSymbolAddress((void**)&b2s, g_bn2s);
    float* b2t;   cudaGetSymbolAddress((void**)&b2t, g_bn2t);

    int prepN = 72 * 4096 + 4 * 16 * 4096 + 2304 * 32;
    prep_weights<<<(prepN + 255) / 256, 256>>>(w_off, w_dcn, w_up);   // idx 0
    conv_off_kernel<<<NB * 64, 256>>>(x, b_off);                      // idx 1
    dummy_kernel<<<1, 32>>>();                                        // idx 2
    mdcn_mma_kernel<<<NB * 64, 256, MD_SMEM>>>(x, b_dcn);             // idx 3 (ncu slot)
    bn_stats_kernel<<<128, 1024>>>(yptr, 12, gamma1, beta1, b1s, b1t);
    deconv_mma_kernel<<<NB * 256, 256, DC_SMEM>>>();
    bn_stats_kernel<<<128, 1024>>>(uptr, 14, gamma2, beta2, b2s, b2t);
    final_kernel<<<(NB * 128 * 128 * 128) / 1024, 256>>>((float*)d_out);
}